// round 11
// baseline (speedup 1.0000x reference)
#include <cuda_runtime.h>
#include <cstdint>
#include <cstddef>

#define DD 100
#define GS 128           // padded g row stride (floats)
#define CT 128           // chunk of timesteps per phase
#define BMAX 128

// g ring: [B][2][CT][GS] floats = 16.8 MB -> L2-resident
static __device__ float g_ring[(size_t)BMAX * 2 * CT * GS];

__device__ __forceinline__ float tanh_ap(float x) {
    float y; asm("tanh.approx.f32 %0, %1;" : "=f"(y) : "f"(x)); return y;
}
__device__ __forceinline__ float rcp_ap(float x) {
    float y; asm("rcp.approx.f32 %0, %1;" : "=f"(y) : "f"(x)); return y;
}
__device__ __forceinline__ float ex2_ap(float x) {
    float y; asm("ex2.approx.f32 %0, %1;" : "=f"(y) : "f"(x)); return y;
}
__device__ __forceinline__ int redux_add_i32(int v) {
    int r;
    asm("redux.sync.add.s32 %0, %1, 0xffffffff;" : "=r"(r) : "r"(v));
    return r;
}

#define MAGICF 12582912.f          /* 1.5 * 2^23 */
#define MAGICI 0x4B400000
#define GSCALE 131072.f            /* 2^17: quant err 2^-18/partial; encode-safe
                                      since |partial| << 32 -> |partial*2^17| < 2^22 */
#define RSC (1.44269504f / 131072.f)

// ---------------------------------------------------------------------------
// Fused kernel: one block per batch b, 256 threads.
//   warp 0      : sequential scan (chunk c-1 during phase c)
//   warps 1..7  : GEMM g[t][c] = sum_e W[c][e] h[t][e] for chunk c
// Weights (w_r cols + w_c + ds_b + 0) in static SMEM, g via L2 ring,
// pre via SMEM double buffer. Only __syncthreads between phases.
// Fixed-point reduce: magic-add encode (fast), exact I2F decode (range-safe).
// ---------------------------------------------------------------------------
__global__ void __launch_bounds__(256, 1)
fused_kernel(const float* __restrict__ h, const float* __restrict__ dvec,
             const float* __restrict__ w_c, const float* __restrict__ w_s,
             const float* __restrict__ w_r, const float* __restrict__ pos,
             const float* __restrict__ w_ap, const float* __restrict__ bscal,
             float* __restrict__ out, int B, int T) {
    __shared__ float ws[DD * 104];             // [e][104] ext. weights 41600 B
    __shared__ float dsS[DD];
    __shared__ __align__(16) float wapS[DD];
    __shared__ float preS[2][CT];

    int b    = blockIdx.x;
    int tid  = threadIdx.x;
    int wid  = tid >> 5;
    int lane = tid & 31;

    // ---------------- prologue ----------------
    // ds[e] = sum_d dvec[b][d] * w_s[d][e]   (coalesced over e)
    if (tid < DD) {
        const float* dv = dvec + b * DD;
        float acc = 0.f;
        #pragma unroll 4
        for (int d = 0; d < DD; ++d)
            acc = fmaf(dv[d], w_s[d * DD + tid], acc);
        dsS[tid] = acc;
    }
    if (tid >= 128 && tid < 128 + DD) wapS[tid - 128] = w_ap[tid - 128];
    __syncthreads();

    // ws[e][c]: c<100 -> w_r[c][e] (coalesced read), 100->w_c, 101->ds, 102/103->0
    for (int idx = tid; idx < DD * DD; idx += 256) {
        int e = idx % DD;
        int c = idx / DD;
        ws[e * 104 + c] = w_r[idx];
    }
    for (int e = tid; e < DD; e += 256) {
        ws[e * 104 + 100] = w_c[e];
        ws[e * 104 + 101] = dsS[e];
        ws[e * 104 + 102] = 0.f;
        ws[e * 104 + 103] = 0.f;
    }
    __syncthreads();

    int NC = (T + CT - 1) / CT;

    // scan state (warp 0): lane L owns dims 4L..4L+3
    float sx = 0.f, sy = 0.f, sz = 0.f, sw = 0.f;
    float gscale = (lane < 25) ? GSCALE : 0.f;
    int   offE   = (lane < 25) ? 4 * lane : 96;

    const float4* ws4  = (const float4*)ws;    // row stride 26
    const float4* wap4 = (const float4*)wapS;  // 25 float4

    for (int c = 0; c <= NC; ++c) {
        // ---------------- GEMM persona: chunk c ----------------
        if (wid > 0 && c < NC) {
            int t0 = c * CT;
            int tid2 = tid - 32;   // 0..223

            if (tid2 < 208) {
                int p  = tid2 % 13;
                int tg = tid2 / 13;

                const float* hr[8];
                #pragma unroll
                for (int i = 0; i < 8; ++i) {
                    int t = t0 + 8 * tg + i; if (t >= T) t = T - 1;
                    hr[i] = h + ((size_t)b * T + t) * DD;
                }

                // p==12 threads own the pre column: apos for their 8 rows
                // inline (pos rows are L2-resident; shared across blocks).
                float ap8[8];
                if (p == 12) {
                    #pragma unroll
                    for (int i = 0; i < 8; ++i) {
                        int t = t0 + 8 * tg + i; if (t >= T) t = T - 1;
                        const float4* pr = (const float4*)(pos + (size_t)t * DD);
                        float ac0 = 0.f, ac1 = 0.f;
                        #pragma unroll
                        for (int k = 0; k < 25; ++k) {
                            float4 pv = pr[k];
                            float4 wv = wap4[k];
                            ac0 = fmaf(pv.x, wv.x, ac0);
                            ac1 = fmaf(pv.y, wv.y, ac1);
                            ac0 = fmaf(pv.z, wv.z, ac0);
                            ac1 = fmaf(pv.w, wv.w, ac1);
                        }
                        ap8[i] = ac0 + ac1;
                    }
                }

                float4 a0[8], a1[8];
                #pragma unroll
                for (int i = 0; i < 8; ++i) {
                    a0[i] = make_float4(0.f, 0.f, 0.f, 0.f);
                    a1[i] = make_float4(0.f, 0.f, 0.f, 0.f);
                }

                for (int e4 = 0; e4 < 25; ++e4) {
                    float4 hq[8];
                    #pragma unroll
                    for (int i = 0; i < 8; ++i)
                        hq[i] = *(const float4*)(hr[i] + 4 * e4);
                    #pragma unroll
                    for (int k = 0; k < 4; ++k) {
                        int e = 4 * e4 + k;
                        float4 w0 = ws4[e * 26 + p];
                        float4 w1 = ws4[e * 26 + 13 + p];
                        #pragma unroll
                        for (int i = 0; i < 8; ++i) {
                            float hh = (k == 0) ? hq[i].x : (k == 1) ? hq[i].y
                                      : (k == 2) ? hq[i].z : hq[i].w;
                            a0[i].x = fmaf(hh, w0.x, a0[i].x);
                            a0[i].y = fmaf(hh, w0.y, a0[i].y);
                            a0[i].z = fmaf(hh, w0.z, a0[i].z);
                            a0[i].w = fmaf(hh, w0.w, a0[i].w);
                            a1[i].x = fmaf(hh, w1.x, a1[i].x);
                            a1[i].y = fmaf(hh, w1.y, a1[i].y);
                            a1[i].z = fmaf(hh, w1.z, a1[i].z);
                            a1[i].w = fmaf(hh, w1.w, a1[i].w);
                        }
                    }
                }

                float bias = bscal[0];
                float* gbase = g_ring + (size_t)(b * 2 + (c & 1)) * CT * GS;
                #pragma unroll
                for (int i = 0; i < 8; ++i) {
                    int tl = 8 * tg + i;
                    if (t0 + tl < T) {
                        float* gr = gbase + (size_t)tl * GS;
                        *(float4*)(gr + 4 * p) = a0[i];
                        if (p < 12) {
                            *(float4*)(gr + 52 + 4 * p) = a1[i];
                        } else {
                            // cols 100..101 = content, salience
                            preS[c & 1][tl] = a1[i].x + a1[i].y + ap8[i] + bias;
                        }
                    }
                }
            }
        }

        // ---------------- scan persona: chunk c-1 ----------------
        if (wid == 0 && c > 0) {
            int cc  = c - 1;
            int t0s = cc * CT;
            int n   = T - t0s; if (n > CT) n = CT;
            const float*  gb     = g_ring + (size_t)(b * 2 + (cc & 1)) * CT * GS;
            const float*  preRow = preS[cc & 1];
            const float*  hbp    = h + ((size_t)b * T + t0s) * DD;
            float*        ob     = out + (size_t)b * T + t0s;

            int start = 0;
            if (cc == 0) {
                // t==0: s=0 -> nov=0, no state update
                float z = preRow[0];
                float q = ex2_ap(z * -1.44269504f);
                ob[0] = rcp_ap(1.f + q);       // all lanes, same value
                start = 1;
            }

            float4 G[8], A[8];
            float PHC[8];
#define LDX(JJ, SL) do {                                                   \
                int _jc = (JJ); if (_jc > n - 1) _jc = n - 1;              \
                float4 _g = *(const float4*)(gb + (size_t)_jc * GS + offE);\
                _g.x *= gscale; _g.y *= gscale;                            \
                _g.z *= gscale; _g.w *= gscale;                            \
                G[SL] = _g;                                                \
                A[SL] = *(const float4*)(hbp + (size_t)_jc * DD + offE);   \
                PHC[SL] = preRow[_jc] * -1.44269504f;                      \
            } while (0)

            #pragma unroll
            for (int k = 0; k < 8; ++k) LDX(start + k, (start + k) & 7);

            #pragma unroll 4
            for (int tl = start; tl < n; ++tl) {
                int sl = tl & 7;
                float4 g = G[sl];
                float4 a = A[sl];
                float phc = PHC[sl];
                LDX(tl + 8, sl);

                float ux = tanh_ap(sx), uy = tanh_ap(sy);
                float uz = tanh_ap(sz), uw = tanh_ap(sw);
                float m0 = ux * g.x;
                float m1 = uy * g.y;
                m0 = fmaf(uz, g.z, m0);
                m1 = fmaf(uw, g.w, m1);
                // encode: float -> fixed via magic add (exact rn, range-safe)
                float tmag = (m0 + m1) + MAGICF;
                int   ri   = __float_as_int(tmag) - MAGICI;
                int   rs   = redux_add_i32(ri);
                // decode: exact I2F (handles full int32 range)
                float fb   = __int2float_rn(rs);

                float zz = fmaf(fb, RSC, phc);
                float q  = ex2_ap(zz);
                float pp = rcp_ap(1.f + q);

                sx = fmaf(a.x, pp, sx);
                sy = fmaf(a.y, pp, sy);
                sz = fmaf(a.z, pp, sz);
                sw = fmaf(a.w, pp, sw);

                ob[tl] = pp;                   // all lanes, same value
            }
#undef LDX
        }

        __syncthreads();   // phase boundary: g/pre of chunk c now visible
    }
}

// ---------------------------------------------------------------------------
extern "C" void kernel_launch(void* const* d_in, const int* in_sizes, int n_in,
                              void* d_out, int out_size) {
    const float* h    = (const float*)d_in[0];  // [B,T,D]
    const float* dv   = (const float*)d_in[1];  // [B,1,D]
    const float* w_c  = (const float*)d_in[2];  // [D,1]
    const float* w_s  = (const float*)d_in[3];  // [D,D]
    const float* w_r  = (const float*)d_in[4];  // [D,D]
    const float* pos  = (const float*)d_in[5];  // [3000,D]
    const float* w_ap = (const float*)d_in[6];  // [D,1]
    const float* bsc  = (const float*)d_in[7];  // [1]
    float* out = (float*)d_out;

    int B = in_sizes[1] / DD;
    int T = in_sizes[0] / (B * DD);

    fused_kernel<<<B, 256>>>(h, dv, w_c, w_s, w_r, pos, w_ap, bsc, out, B, T);
}

// round 12
// speedup vs baseline: 1.3359x; 1.3359x over previous
#include <cuda_runtime.h>
#include <cstdint>
#include <cstddef>

#define DD 100
#define GS 128           // padded g row stride (floats)
#define CT 96            // chunk of timesteps per phase
#define BMAX 128

// g ring: [B][2][CT][GS] floats = 12.6 MB -> L2-resident
static __device__ float g_ring[(size_t)BMAX * 2 * CT * GS];

__device__ __forceinline__ float tanh_ap(float x) {
    float y; asm("tanh.approx.f32 %0, %1;" : "=f"(y) : "f"(x)); return y;
}
__device__ __forceinline__ float rcp_ap(float x) {
    float y; asm("rcp.approx.f32 %0, %1;" : "=f"(y) : "f"(x)); return y;
}
__device__ __forceinline__ float ex2_ap(float x) {
    float y; asm("ex2.approx.f32 %0, %1;" : "=f"(y) : "f"(x)); return y;
}
__device__ __forceinline__ int redux_add_i32(int v) {
    int r;
    asm("redux.sync.add.s32 %0, %1, 0xffffffff;" : "=r"(r) : "r"(v));
    return r;
}

#define MAGICF 12582912.f          /* 1.5 * 2^23 */
#define MAGICI 0x4B400000
#define GSCALE 131072.f            /* 2^17 fixed-point scale (R11-validated) */
#define RSC (1.44269504f / 131072.f)

// ---------------------------------------------------------------------------
// Fused kernel: one block per batch b, 512 threads.
//   warp 0              : sequential scan (chunk c-1) -- ALONE on SMSP0
//   warps w, w%4 != 0   : GEMM for chunk c (12 warps on SMSPs 1..3)
//   warps 4, 8, 12      : idle (barrier only) -- keep SMSP0 clear of work
// Scan ring depth 4 with unroll 4 -> slot indices constant -> registers.
// GEMM: 312 threads, 4t x 8c tile (32 acc regs) -> no spills at 512 thr.
// ---------------------------------------------------------------------------
__global__ void __launch_bounds__(512, 1)
fused_kernel(const float* __restrict__ h, const float* __restrict__ dvec,
             const float* __restrict__ w_c, const float* __restrict__ w_s,
             const float* __restrict__ w_r, const float* __restrict__ pos,
             const float* __restrict__ w_ap, const float* __restrict__ bscal,
             float* __restrict__ out, int B, int T) {
    __shared__ float ws[DD * 104];             // [e][104] ext. weights 41600 B
    __shared__ float dsS[DD];
    __shared__ __align__(16) float wapS[DD];
    __shared__ float preS[2][CT];

    int b    = blockIdx.x;
    int tid  = threadIdx.x;
    int wid  = tid >> 5;
    int lane = tid & 31;

    // ---------------- prologue ----------------
    if (tid < DD) {
        const float* dv = dvec + b * DD;
        float acc = 0.f;
        #pragma unroll 4
        for (int d = 0; d < DD; ++d)
            acc = fmaf(dv[d], w_s[d * DD + tid], acc);
        dsS[tid] = acc;
    }
    if (tid >= 128 && tid < 128 + DD) wapS[tid - 128] = w_ap[tid - 128];
    __syncthreads();

    // ws[e][c]: c<100 -> w_r[c][e], 100->w_c, 101->ds, 102/103->0
    for (int idx = tid; idx < DD * DD; idx += 512) {
        int e = idx % DD;
        int c = idx / DD;
        ws[e * 104 + c] = w_r[idx];
    }
    for (int e = tid; e < DD; e += 512) {
        ws[e * 104 + 100] = w_c[e];
        ws[e * 104 + 101] = dsS[e];
        ws[e * 104 + 102] = 0.f;
        ws[e * 104 + 103] = 0.f;
    }
    __syncthreads();

    int NC = (T + CT - 1) / CT;

    // scan state (warp 0): lane L owns dims 4L..4L+3
    float sx = 0.f, sy = 0.f, sz = 0.f, sw = 0.f;
    float gscale = (lane < 25) ? GSCALE : 0.f;
    int   offE   = (lane < 25) ? 4 * lane : 96;

    const float4* ws4  = (const float4*)ws;    // row stride 26
    const float4* wap4 = (const float4*)wapS;  // 25 float4

    for (int c = 0; c <= NC; ++c) {
        // ---------------- GEMM persona: chunk c ----------------
        if ((wid & 3) != 0 && c < NC) {
            int t0 = c * CT;
            int gw   = wid - 1 - (wid >> 2);   // 0..11 compact GEMM warp idx
            int gtid = gw * 32 + lane;         // 0..383

            if (gtid < 312) {
                int p  = gtid % 13;            // col quad
                int tg = gtid / 13;            // 0..23 -> rows 4tg..4tg+3

                const float* hr[4];
                #pragma unroll
                for (int i = 0; i < 4; ++i) {
                    int t = t0 + 4 * tg + i; if (t >= T) t = T - 1;
                    hr[i] = h + ((size_t)b * T + t) * DD;
                }

                // p==12 threads own the pre column: inline apos for 4 rows.
                float ap4[4];
                if (p == 12) {
                    #pragma unroll
                    for (int i = 0; i < 4; ++i) {
                        int t = t0 + 4 * tg + i; if (t >= T) t = T - 1;
                        const float4* pr = (const float4*)(pos + (size_t)t * DD);
                        float ac0 = 0.f, ac1 = 0.f;
                        #pragma unroll
                        for (int k = 0; k < 25; ++k) {
                            float4 pv = pr[k];
                            float4 wv = wap4[k];
                            ac0 = fmaf(pv.x, wv.x, ac0);
                            ac1 = fmaf(pv.y, wv.y, ac1);
                            ac0 = fmaf(pv.z, wv.z, ac0);
                            ac1 = fmaf(pv.w, wv.w, ac1);
                        }
                        ap4[i] = ac0 + ac1;
                    }
                }

                float4 a0[4], a1[4];
                #pragma unroll
                for (int i = 0; i < 4; ++i) {
                    a0[i] = make_float4(0.f, 0.f, 0.f, 0.f);
                    a1[i] = make_float4(0.f, 0.f, 0.f, 0.f);
                }

                for (int e4 = 0; e4 < 25; ++e4) {
                    float4 hq[4];
                    #pragma unroll
                    for (int i = 0; i < 4; ++i)
                        hq[i] = *(const float4*)(hr[i] + 4 * e4);
                    #pragma unroll
                    for (int k = 0; k < 4; ++k) {
                        int e = 4 * e4 + k;
                        float4 w0 = ws4[e * 26 + p];
                        float4 w1 = ws4[e * 26 + 13 + p];
                        #pragma unroll
                        for (int i = 0; i < 4; ++i) {
                            float hh = (k == 0) ? hq[i].x : (k == 1) ? hq[i].y
                                      : (k == 2) ? hq[i].z : hq[i].w;
                            a0[i].x = fmaf(hh, w0.x, a0[i].x);
                            a0[i].y = fmaf(hh, w0.y, a0[i].y);
                            a0[i].z = fmaf(hh, w0.z, a0[i].z);
                            a0[i].w = fmaf(hh, w0.w, a0[i].w);
                            a1[i].x = fmaf(hh, w1.x, a1[i].x);
                            a1[i].y = fmaf(hh, w1.y, a1[i].y);
                            a1[i].z = fmaf(hh, w1.z, a1[i].z);
                            a1[i].w = fmaf(hh, w1.w, a1[i].w);
                        }
                    }
                }

                float bias = bscal[0];
                float* gbase = g_ring + (size_t)(b * 2 + (c & 1)) * CT * GS;
                #pragma unroll
                for (int i = 0; i < 4; ++i) {
                    int tl = 4 * tg + i;
                    if (t0 + tl < T) {
                        float* gr = gbase + (size_t)tl * GS;
                        *(float4*)(gr + 4 * p) = a0[i];
                        if (p < 12) {
                            *(float4*)(gr + 52 + 4 * p) = a1[i];
                        } else {
                            // cols 100..101 = content, salience
                            preS[c & 1][tl] = a1[i].x + a1[i].y + ap4[i] + bias;
                        }
                    }
                }
            }
        }

        // ---------------- scan persona: chunk c-1 (warp 0 only) ----------
        if (wid == 0 && c > 0) {
            int cc  = c - 1;
            int t0s = cc * CT;
            int n   = T - t0s; if (n > CT) n = CT;
            const float*  gb     = g_ring + (size_t)(b * 2 + (cc & 1)) * CT * GS;
            const float*  preRow = preS[cc & 1];
            const float*  hbp    = h + ((size_t)b * T + t0s) * DD;
            float*        ob     = out + (size_t)b * T + t0s;

            float4 G[4], A[4];
            float PHC[4];
            // LDX: branchless clamped load; A zeroed for global t==0 (the
            // reference skips the state update at j==0; tanh(0)=0 already
            // makes nov_0 = 0).
#define LDX(JJ, SL) do {                                                   \
                int _jc = (JJ); if (_jc > n - 1) _jc = n - 1;              \
                float4 _g = *(const float4*)(gb + (size_t)_jc * GS + offE);\
                _g.x *= gscale; _g.y *= gscale;                            \
                _g.z *= gscale; _g.w *= gscale;                            \
                G[SL] = _g;                                                \
                float4 _a = *(const float4*)(hbp + (size_t)_jc * DD + offE);\
                float _m = (t0s + _jc == 0) ? 0.f : 1.f;                   \
                _a.x *= _m; _a.y *= _m; _a.z *= _m; _a.w *= _m;            \
                A[SL] = _a;                                                \
                PHC[SL] = preRow[_jc] * -1.44269504f;                      \
            } while (0)

            LDX(0, 0); LDX(1, 1); LDX(2, 2); LDX(3, 3);

            #pragma unroll 4
            for (int tl = 0; tl < n; ++tl) {
                int sl = tl & 3;
                float4 g = G[sl];
                float4 a = A[sl];
                float phc = PHC[sl];
                LDX(tl + 4, sl);

                float ux = tanh_ap(sx), uy = tanh_ap(sy);
                float uz = tanh_ap(sz), uw = tanh_ap(sw);
                float m0 = ux * g.x;
                float m1 = uy * g.y;
                m0 = fmaf(uz, g.z, m0);
                m1 = fmaf(uw, g.w, m1);
                // encode: float -> fixed via magic add (exact rn, range-safe)
                float tmag = (m0 + m1) + MAGICF;
                int   ri   = __float_as_int(tmag) - MAGICI;
                int   rs   = redux_add_i32(ri);
                // decode: exact I2F
                float fb   = __int2float_rn(rs);

                float zz = fmaf(fb, RSC, phc);
                float q  = ex2_ap(zz);
                float pp = rcp_ap(1.f + q);

                sx = fmaf(a.x, pp, sx);
                sy = fmaf(a.y, pp, sy);
                sz = fmaf(a.z, pp, sz);
                sw = fmaf(a.w, pp, sw);

                ob[tl] = pp;                   // all lanes, same value
            }
#undef LDX
        }

        __syncthreads();   // phase boundary: g/pre of chunk c now visible
    }
}

// ---------------------------------------------------------------------------
extern "C" void kernel_launch(void* const* d_in, const int* in_sizes, int n_in,
                              void* d_out, int out_size) {
    const float* h    = (const float*)d_in[0];  // [B,T,D]
    const float* dv   = (const float*)d_in[1];  // [B,1,D]
    const float* w_c  = (const float*)d_in[2];  // [D,1]
    const float* w_s  = (const float*)d_in[3];  // [D,D]
    const float* w_r  = (const float*)d_in[4];  // [D,D]
    const float* pos  = (const float*)d_in[5];  // [3000,D]
    const float* w_ap = (const float*)d_in[6];  // [D,1]
    const float* bsc  = (const float*)d_in[7];  // [1]
    float* out = (float*)d_out;

    int B = in_sizes[1] / DD;
    int T = in_sizes[0] / (B * DD);

    fused_kernel<<<B, 512>>>(h, dv, w_c, w_s, w_r, pos, w_ap, bsc, out, B, T);
}

// round 13
// speedup vs baseline: 1.4359x; 1.0748x over previous
#include <cuda_runtime.h>
#include <cstdint>
#include <cstddef>

#define DD 100
#define GS 128           // padded g row stride (floats)
#define CT 96            // chunk of timesteps per phase
#define BMAX 128

// g ring: [B][2][CT][GS] floats = 12.6 MB -> L2-resident
static __device__ float g_ring[(size_t)BMAX * 2 * CT * GS];

__device__ __forceinline__ float tanh_ap(float x) {
    float y; asm("tanh.approx.f32 %0, %1;" : "=f"(y) : "f"(x)); return y;
}
__device__ __forceinline__ float rcp_ap(float x) {
    float y; asm("rcp.approx.f32 %0, %1;" : "=f"(y) : "f"(x)); return y;
}
__device__ __forceinline__ float ex2_ap(float x) {
    float y; asm("ex2.approx.f32 %0, %1;" : "=f"(y) : "f"(x)); return y;
}
__device__ __forceinline__ int redux_add_i32(int v) {
    int r;
    asm("redux.sync.add.s32 %0, %1, 0xffffffff;" : "=r"(r) : "r"(v));
    return r;
}
// packed fp32x2: d = a*b + d (elementwise, IEEE fp32 per lane)
__device__ __forceinline__ void ffma2(unsigned long long& d,
                                      unsigned long long a,
                                      unsigned long long b) {
    asm("fma.rn.f32x2 %0, %1, %2, %0;" : "+l"(d) : "l"(a), "l"(b));
}
__device__ __forceinline__ unsigned long long pack2(float x) {
    unsigned long long r;
    asm("mov.b64 %0, {%1, %1};" : "=l"(r) : "r"(__float_as_uint(x)));
    return r;
}
__device__ __forceinline__ void unpack2(unsigned long long v, float& lo, float& hi) {
    unsigned int a, bq;
    asm("mov.b64 {%0, %1}, %2;" : "=r"(a), "=r"(bq) : "l"(v));
    lo = __uint_as_float(a); hi = __uint_as_float(bq);
}

#define MAGICF 12582912.f          /* 1.5 * 2^23 */
#define MAGICI 0x4B400000
#define GSCALE 131072.f            /* 2^17 fixed-point scale (validated) */
#define RSC (1.44269504f / 131072.f)

// ---------------------------------------------------------------------------
// Fused kernel: one block per batch b, 512 threads.
//   warps 0..9  : GEMM for chunk c (312 active threads, 4t x 8c, FFMA2)
//                 SMSP loads: 3/3/2/2 warps -> max 4800 ffma2 = 9.6K cy
//   warps 10..14: idle (barrier only)
//   warp 15     : sequential scan (chunk c-1) -- SMSP3, HIGHEST wid ->
//                 wins hi-wid-first arbitration over SMSP3's 2 GEMM warps
// ---------------------------------------------------------------------------
__global__ void __launch_bounds__(512, 1)
fused_kernel(const float* __restrict__ h, const float* __restrict__ dvec,
             const float* __restrict__ w_c, const float* __restrict__ w_s,
             const float* __restrict__ w_r, const float* __restrict__ pos,
             const float* __restrict__ w_ap, const float* __restrict__ bscal,
             float* __restrict__ out, int B, int T) {
    __shared__ float ws[DD * 104];             // [e][104] ext. weights 41600 B
    __shared__ float dsS[DD];
    __shared__ __align__(16) float wapS[DD];
    __shared__ float preS[2][CT];

    int b    = blockIdx.x;
    int tid  = threadIdx.x;
    int wid  = tid >> 5;
    int lane = tid & 31;

    // ---------------- prologue ----------------
    if (tid < DD) {
        const float* dv = dvec + b * DD;
        float acc = 0.f;
        #pragma unroll 4
        for (int d = 0; d < DD; ++d)
            acc = fmaf(dv[d], w_s[d * DD + tid], acc);
        dsS[tid] = acc;
    }
    if (tid >= 128 && tid < 128 + DD) wapS[tid - 128] = w_ap[tid - 128];
    __syncthreads();

    // ws[e][c]: c<100 -> w_r[c][e], 100->w_c, 101->ds, 102/103->0
    for (int idx = tid; idx < DD * DD; idx += 512) {
        int e = idx % DD;
        int c = idx / DD;
        ws[e * 104 + c] = w_r[idx];
    }
    for (int e = tid; e < DD; e += 512) {
        ws[e * 104 + 100] = w_c[e];
        ws[e * 104 + 101] = dsS[e];
        ws[e * 104 + 102] = 0.f;
        ws[e * 104 + 103] = 0.f;
    }
    __syncthreads();

    int NC = (T + CT - 1) / CT;

    // scan state (warp 15): lane L owns dims 4L..4L+3
    float sx = 0.f, sy = 0.f, sz = 0.f, sw = 0.f;
    float gscale = (lane < 25) ? GSCALE : 0.f;
    int   offE   = (lane < 25) ? 4 * lane : 96;

    const ulonglong2* ws8  = (const ulonglong2*)ws;   // row stride 26 (16B units)
    const float4*     wap4 = (const float4*)wapS;     // 25 float4

    for (int c = 0; c <= NC; ++c) {
        // ---------------- GEMM persona: chunk c (warps 0..9) -------------
        if (wid < 10 && c < NC) {
            int t0   = c * CT;
            int gtid = wid * 32 + lane;    // 0..319

            if (gtid < 312) {
                int p  = gtid % 13;        // col quad
                int tg = gtid / 13;        // 0..23 -> rows 4tg..4tg+3

                const float* hr[4];
                #pragma unroll
                for (int i = 0; i < 4; ++i) {
                    int t = t0 + 4 * tg + i; if (t >= T) t = T - 1;
                    hr[i] = h + ((size_t)b * T + t) * DD;
                }

                // p==12 threads own the pre column: inline apos for 4 rows.
                float ap4[4];
                if (p == 12) {
                    #pragma unroll
                    for (int i = 0; i < 4; ++i) {
                        int t = t0 + 4 * tg + i; if (t >= T) t = T - 1;
                        const float4* pr = (const float4*)(pos + (size_t)t * DD);
                        float ac0 = 0.f, ac1 = 0.f;
                        #pragma unroll
                        for (int k = 0; k < 25; ++k) {
                            float4 pv = pr[k];
                            float4 wv = wap4[k];
                            ac0 = fmaf(pv.x, wv.x, ac0);
                            ac1 = fmaf(pv.y, wv.y, ac1);
                            ac0 = fmaf(pv.z, wv.z, ac0);
                            ac1 = fmaf(pv.w, wv.w, ac1);
                        }
                        ap4[i] = ac0 + ac1;
                    }
                }

                // accumulators: 4 rows x 8 cols as packed f32x2 (16 u64)
                unsigned long long A0[4][2], A1[4][2];
                #pragma unroll
                for (int i = 0; i < 4; ++i) {
                    A0[i][0] = 0ull; A0[i][1] = 0ull;
                    A1[i][0] = 0ull; A1[i][1] = 0ull;
                }

                for (int e4 = 0; e4 < 25; ++e4) {
                    float4 hq[4];
                    #pragma unroll
                    for (int i = 0; i < 4; ++i)
                        hq[i] = *(const float4*)(hr[i] + 4 * e4);
                    #pragma unroll
                    for (int k = 0; k < 4; ++k) {
                        int e = 4 * e4 + k;
                        ulonglong2 w0 = ws8[e * 26 + p];       // cols 4p..4p+3
                        ulonglong2 w1 = ws8[e * 26 + 13 + p];  // cols 52+4p..
                        #pragma unroll
                        for (int i = 0; i < 4; ++i) {
                            float hh = (k == 0) ? hq[i].x : (k == 1) ? hq[i].y
                                      : (k == 2) ? hq[i].z : hq[i].w;
                            unsigned long long h2 = pack2(hh);
                            ffma2(A0[i][0], h2, w0.x);
                            ffma2(A0[i][1], h2, w0.y);
                            ffma2(A1[i][0], h2, w1.x);
                            ffma2(A1[i][1], h2, w1.y);
                        }
                    }
                }

                float bias = bscal[0];
                float* gbase = g_ring + (size_t)(b * 2 + (c & 1)) * CT * GS;
                #pragma unroll
                for (int i = 0; i < 4; ++i) {
                    int tl = 4 * tg + i;
                    if (t0 + tl < T) {
                        float* gr = gbase + (size_t)tl * GS;
                        *(ulonglong2*)(gr + 4 * p) =
                            make_ulonglong2(A0[i][0], A0[i][1]);
                        if (p < 12) {
                            *(ulonglong2*)(gr + 52 + 4 * p) =
                                make_ulonglong2(A1[i][0], A1[i][1]);
                        } else {
                            // cols 100..101 = content, salience
                            float c0, c1;
                            unpack2(A1[i][0], c0, c1);
                            preS[c & 1][tl] = c0 + c1 + ap4[i] + bias;
                        }
                    }
                }
            }
        }

        // ---------------- scan persona: chunk c-1 (warp 15) --------------
        if (wid == 15 && c > 0) {
            int cc  = c - 1;
            int t0s = cc * CT;
            int n   = T - t0s; if (n > CT) n = CT;
            const float*  gb     = g_ring + (size_t)(b * 2 + (cc & 1)) * CT * GS;
            const float*  preRow = preS[cc & 1];
            const float*  hbp    = h + ((size_t)b * T + t0s) * DD;
            float*        ob     = out + (size_t)b * T + t0s;

            float4 G[4], A[4];
            float PHC[4];
            // LDX: branchless clamped load; A zeroed for global t==0 (the
            // reference skips the state update at j==0; tanh(0)=0 already
            // makes nov_0 = 0).
#define LDX(JJ, SL) do {                                                   \
                int _jc = (JJ); if (_jc > n - 1) _jc = n - 1;              \
                float4 _g = *(const float4*)(gb + (size_t)_jc * GS + offE);\
                _g.x *= gscale; _g.y *= gscale;                            \
                _g.z *= gscale; _g.w *= gscale;                            \
                G[SL] = _g;                                                \
                float4 _a = *(const float4*)(hbp + (size_t)_jc * DD + offE);\
                float _m = (t0s + _jc == 0) ? 0.f : 1.f;                   \
                _a.x *= _m; _a.y *= _m; _a.z *= _m; _a.w *= _m;            \
                A[SL] = _a;                                                \
                PHC[SL] = preRow[_jc] * -1.44269504f;                      \
            } while (0)

            LDX(0, 0); LDX(1, 1); LDX(2, 2); LDX(3, 3);

            #pragma unroll 4
            for (int tl = 0; tl < n; ++tl) {
                int sl = tl & 3;
                float4 g = G[sl];
                float4 a = A[sl];
                float phc = PHC[sl];
                LDX(tl + 4, sl);

                float ux = tanh_ap(sx), uy = tanh_ap(sy);
                float uz = tanh_ap(sz), uw = tanh_ap(sw);
                // MAGICF folded into the m1 chain: tmag = partial + MAGICF
                float m1 = fmaf(uy, g.y, MAGICF);
                float m0 = ux * g.x;
                m0 = fmaf(uz, g.z, m0);
                m1 = fmaf(uw, g.w, m1);
                float tmag = m0 + m1;
                int   ri   = __float_as_int(tmag) - MAGICI;
                int   rs   = redux_add_i32(ri);
                float fb   = __int2float_rn(rs);

                float zz = fmaf(fb, RSC, phc);
                float q  = ex2_ap(zz);
                float pp = rcp_ap(1.f + q);

                sx = fmaf(a.x, pp, sx);
                sy = fmaf(a.y, pp, sy);
                sz = fmaf(a.z, pp, sz);
                sw = fmaf(a.w, pp, sw);

                ob[tl] = pp;                   // all lanes, same value
            }
#undef LDX
        }

        __syncthreads();   // phase boundary: g/pre of chunk c now visible
    }
}

// ---------------------------------------------------------------------------
extern "C" void kernel_launch(void* const* d_in, const int* in_sizes, int n_in,
                              void* d_out, int out_size) {
    const float* h    = (const float*)d_in[0];  // [B,T,D]
    const float* dv   = (const float*)d_in[1];  // [B,1,D]
    const float* w_c  = (const float*)d_in[2];  // [D,1]
    const float* w_s  = (const float*)d_in[3];  // [D,D]
    const float* w_r  = (const float*)d_in[4];  // [D,D]
    const float* pos  = (const float*)d_in[5];  // [3000,D]
    const float* w_ap = (const float*)d_in[6];  // [D,1]
    const float* bsc  = (const float*)d_in[7];  // [1]
    float* out = (float*)d_out;

    int B = in_sizes[1] / DD;
    int T = in_sizes[0] / (B * DD);

    fused_kernel<<<B, 512>>>(h, dv, w_c, w_s, w_r, pos, w_ap, bsc, out, B, T);
}

// round 14
// speedup vs baseline: 1.8009x; 1.2543x over previous
#include <cuda_runtime.h>
#include <cstdint>
#include <cstddef>

#define DD 100
#define GS 128           // padded g row stride (floats)
#define CT 128           // chunk of timesteps per phase
#define BMAX 128

// g ring: [B][2][CT][GS] floats = 16.8 MB -> L2-resident
static __device__ float g_ring[(size_t)BMAX * 2 * CT * GS];

__device__ __forceinline__ float tanh_ap(float x) {
    float y; asm("tanh.approx.f32 %0, %1;" : "=f"(y) : "f"(x)); return y;
}
__device__ __forceinline__ float rcp_ap(float x) {
    float y; asm("rcp.approx.f32 %0, %1;" : "=f"(y) : "f"(x)); return y;
}
__device__ __forceinline__ float ex2_ap(float x) {
    float y; asm("ex2.approx.f32 %0, %1;" : "=f"(y) : "f"(x)); return y;
}
__device__ __forceinline__ int redux_add_i32(int v) {
    int r;
    asm("redux.sync.add.s32 %0, %1, 0xffffffff;" : "=r"(r) : "r"(v));
    return r;
}
// packed fp32x2: d = a*b + d (elementwise, IEEE fp32 per lane)
__device__ __forceinline__ void ffma2(unsigned long long& d,
                                      unsigned long long a,
                                      unsigned long long b) {
    asm("fma.rn.f32x2 %0, %1, %2, %0;" : "+l"(d) : "l"(a), "l"(b));
}
__device__ __forceinline__ unsigned long long pack2(float x) {
    unsigned long long r;
    asm("mov.b64 %0, {%1, %1};" : "=l"(r) : "r"(__float_as_uint(x)));
    return r;
}
__device__ __forceinline__ void unpack2(unsigned long long v, float& lo, float& hi) {
    unsigned int a, bq;
    asm("mov.b64 {%0, %1}, %2;" : "=r"(a), "=r"(bq) : "l"(v));
    lo = __uint_as_float(a); hi = __uint_as_float(bq);
}

#define MAGICF 12582912.f          /* 1.5 * 2^23 */
#define MAGICI 0x4B400000
#define GSCALE 131072.f            /* 2^17: folded into GEMM output now */
#define RSC (1.44269504f / 131072.f)
#define NL2E (-1.44269504f)

// ---------------------------------------------------------------------------
// Scan one chunk. FIRST=true only for the chunk containing global t==0
// (masks the state update at t==0; tanh(0)=0 already gives nov_0 = 0).
// g rows are pre-scaled by 2^17; ring cols 100..103 are zero so lanes
// 25..31 (offG=100) contribute exactly 0. preRow already holds -log2e*pre.
// ---------------------------------------------------------------------------
template <bool FIRST>
__device__ __forceinline__ void scan_chunk(
    const float* __restrict__ gb, const float* __restrict__ preRow,
    const float* __restrict__ hbp, float* __restrict__ ob,
    int n, int offG, int offA,
    float& sx, float& sy, float& sz, float& sw) {

    float4 G[8], A[8];
    float PHC[8];

#define LDX(JJ, SL) do {                                                   \
        int _jc = (JJ); if (_jc > n - 1) _jc = n - 1;                      \
        G[SL] = *(const float4*)(gb + (size_t)_jc * GS + offG);            \
        float4 _a = *(const float4*)(hbp + (size_t)_jc * DD + offA);       \
        if (FIRST) {                                                       \
            float _m = (_jc == 0) ? 0.f : 1.f;                             \
            _a.x *= _m; _a.y *= _m; _a.z *= _m; _a.w *= _m;                \
        }                                                                  \
        A[SL] = _a;                                                        \
        PHC[SL] = preRow[_jc];                                             \
    } while (0)

    LDX(0, 0); LDX(1, 1); LDX(2, 2); LDX(3, 3);
    LDX(4, 4); LDX(5, 5); LDX(6, 6); LDX(7, 7);

    #pragma unroll 8
    for (int tl = 0; tl < n; ++tl) {
        int sl = tl & 7;
        float4 g = G[sl];
        float4 a = A[sl];
        float phc = PHC[sl];
        LDX(tl + 8, sl);

        float ux = tanh_ap(sx), uy = tanh_ap(sy);
        float uz = tanh_ap(sz), uw = tanh_ap(sw);
        float m0 = ux * g.x;
        float m1 = uy * g.y;
        m0 = fmaf(uz, g.z, m0);
        m1 = fmaf(uw, g.w, m1);
        // exact fixed-point encode (single final rounding per lane)
        float tmag = (m0 + m1) + MAGICF;
        int   ri   = __float_as_int(tmag) - MAGICI;
        int   rs   = redux_add_i32(ri);
        float fb   = __int2float_rn(rs);            // exact decode

        float zz = fmaf(fb, RSC, phc);              // phc = -log2e*pre
        float q  = ex2_ap(zz);
        float pp = rcp_ap(1.f + q);

        sx = fmaf(a.x, pp, sx);
        sy = fmaf(a.y, pp, sy);
        sz = fmaf(a.z, pp, sz);
        sw = fmaf(a.w, pp, sw);

        ob[tl] = pp;                                // all lanes, same value
    }
#undef LDX
}

// ---------------------------------------------------------------------------
// Fused kernel: one block per batch b, 512 threads.
//   warps 0..12 : GEMM for chunk c (416 threads, 4t x 8c, FFMA2)
//   warps 13,14 : idle (barrier only)
//   warp 15     : sequential scan (chunk c-1), highest wid on SMSP3
// ---------------------------------------------------------------------------
__global__ void __launch_bounds__(512, 1)
fused_kernel(const float* __restrict__ h, const float* __restrict__ dvec,
             const float* __restrict__ w_c, const float* __restrict__ w_s,
             const float* __restrict__ w_r, const float* __restrict__ pos,
             const float* __restrict__ w_ap, const float* __restrict__ bscal,
             float* __restrict__ out, int B, int T) {
    __shared__ float ws[DD * 104];             // [e][104] ext. weights 41600 B
    __shared__ float dsS[DD];
    __shared__ __align__(16) float wapS[DD];
    __shared__ float preS[2][CT];

    int b    = blockIdx.x;
    int tid  = threadIdx.x;
    int wid  = tid >> 5;
    int lane = tid & 31;

    // ---------------- prologue ----------------
    if (tid < DD) {
        const float* dv = dvec + b * DD;
        float acc = 0.f;
        #pragma unroll 4
        for (int d = 0; d < DD; ++d)
            acc = fmaf(dv[d], w_s[d * DD + tid], acc);
        dsS[tid] = acc;
    }
    if (tid >= 128 && tid < 128 + DD) wapS[tid - 128] = w_ap[tid - 128];
    __syncthreads();

    // ws[e][c]: c<100 -> w_r[c][e] * 2^17 (pre-scaled for the scan's
    // fixed-point encode), 100->w_c, 101->ds, 102/103->0 (unscaled: pre path)
    for (int idx = tid; idx < DD * DD; idx += 512) {
        int e = idx % DD;
        int c = idx / DD;
        ws[e * 104 + c] = w_r[idx] * GSCALE;
    }
    for (int e = tid; e < DD; e += 512) {
        ws[e * 104 + 100] = w_c[e];
        ws[e * 104 + 101] = dsS[e];
        ws[e * 104 + 102] = 0.f;
        ws[e * 104 + 103] = 0.f;
    }
    __syncthreads();

    int NC = (T + CT - 1) / CT;

    // scan state (warp 15): lane L owns dims 4L..4L+3
    float sx = 0.f, sy = 0.f, sz = 0.f, sw = 0.f;
    int offG = (lane < 25) ? 4 * lane : 100;   // ring cols 100..103 are zero
    int offA = (lane < 25) ? 4 * lane : 96;    // in-bounds garbage, unused

    const ulonglong2* ws8  = (const ulonglong2*)ws;   // row stride 26
    const float4*     wap4 = (const float4*)wapS;     // 25 float4

    for (int c = 0; c <= NC; ++c) {
        // ---------------- GEMM persona: chunk c (warps 0..12) ------------
        if (wid < 13 && c < NC) {
            int t0   = c * CT;
            int gtid = wid * 32 + lane;    // 0..415
            int p  = gtid % 13;            // col quad
            int tg = gtid / 13;            // 0..31 -> rows 4tg..4tg+3

            const float* hr[4];
            #pragma unroll
            for (int i = 0; i < 4; ++i) {
                int t = t0 + 4 * tg + i; if (t >= T) t = T - 1;
                hr[i] = h + ((size_t)b * T + t) * DD;
            }

            // p==12 threads own the pre column: inline apos for 4 rows.
            float ap4[4];
            if (p == 12) {
                #pragma unroll
                for (int i = 0; i < 4; ++i) {
                    int t = t0 + 4 * tg + i; if (t >= T) t = T - 1;
                    const float4* pr = (const float4*)(pos + (size_t)t * DD);
                    float ac0 = 0.f, ac1 = 0.f;
                    #pragma unroll
                    for (int k = 0; k < 25; ++k) {
                        float4 pv = pr[k];
                        float4 wv = wap4[k];
                        ac0 = fmaf(pv.x, wv.x, ac0);
                        ac1 = fmaf(pv.y, wv.y, ac1);
                        ac0 = fmaf(pv.z, wv.z, ac0);
                        ac1 = fmaf(pv.w, wv.w, ac1);
                    }
                    ap4[i] = ac0 + ac1;
                }
            }

            // accumulators: 4 rows x 8 cols as packed f32x2 (16 u64)
            unsigned long long A0[4][2], A1[4][2];
            #pragma unroll
            for (int i = 0; i < 4; ++i) {
                A0[i][0] = 0ull; A0[i][1] = 0ull;
                A1[i][0] = 0ull; A1[i][1] = 0ull;
            }

            for (int e4 = 0; e4 < 25; ++e4) {
                float4 hq[4];
                #pragma unroll
                for (int i = 0; i < 4; ++i)
                    hq[i] = *(const float4*)(hr[i] + 4 * e4);
                #pragma unroll
                for (int k = 0; k < 4; ++k) {
                    int e = 4 * e4 + k;
                    ulonglong2 w0 = ws8[e * 26 + p];       // cols 4p..4p+3
                    ulonglong2 w1 = ws8[e * 26 + 13 + p];  // cols 52+4p..
                    #pragma unroll
                    for (int i = 0; i < 4; ++i) {
                        float hh = (k == 0) ? hq[i].x : (k == 1) ? hq[i].y
                                  : (k == 2) ? hq[i].z : hq[i].w;
                        unsigned long long h2 = pack2(hh);
                        ffma2(A0[i][0], h2, w0.x);
                        ffma2(A0[i][1], h2, w0.y);
                        ffma2(A1[i][0], h2, w1.x);
                        ffma2(A1[i][1], h2, w1.y);
                    }
                }
            }

            float bias = bscal[0];
            float* gbase = g_ring + (size_t)(b * 2 + (c & 1)) * CT * GS;
            #pragma unroll
            for (int i = 0; i < 4; ++i) {
                int tl = 4 * tg + i;
                if (t0 + tl < T) {
                    float* gr = gbase + (size_t)tl * GS;
                    *(ulonglong2*)(gr + 4 * p) =
                        make_ulonglong2(A0[i][0], A0[i][1]);
                    if (p < 12) {
                        *(ulonglong2*)(gr + 52 + 4 * p) =
                            make_ulonglong2(A1[i][0], A1[i][1]);
                    } else {
                        // ring cols 100..103 <- 0 (dead-lane reads)
                        *(float4*)(gr + 100) = make_float4(0.f, 0.f, 0.f, 0.f);
                        // preS holds -log2e * pre (folds scan's FMUL away)
                        float c0, c1;
                        unpack2(A1[i][0], c0, c1);
                        preS[c & 1][tl] = (c0 + c1 + ap4[i] + bias) * NL2E;
                    }
                }
            }
        }

        // ---------------- scan persona: chunk c-1 (warp 15) --------------
        if (wid == 15 && c > 0) {
            int cc  = c - 1;
            int t0s = cc * CT;
            int n   = T - t0s; if (n > CT) n = CT;
            const float* gb     = g_ring + (size_t)(b * 2 + (cc & 1)) * CT * GS;
            const float* preRow = preS[cc & 1];
            const float* hbp    = h + ((size_t)b * T + t0s) * DD;
            float*       ob     = out + (size_t)b * T + t0s;

            if (cc == 0)
                scan_chunk<true>(gb, preRow, hbp, ob, n, offG, offA,
                                 sx, sy, sz, sw);
            else
                scan_chunk<false>(gb, preRow, hbp, ob, n, offG, offA,
                                  sx, sy, sz, sw);
        }

        __syncthreads();   // phase boundary: g/pre of chunk c now visible
    }
}

// ---------------------------------------------------------------------------
extern "C" void kernel_launch(void* const* d_in, const int* in_sizes, int n_in,
                              void* d_out, int out_size) {
    const float* h    = (const float*)d_in[0];  // [B,T,D]
    const float* dv   = (const float*)d_in[1];  // [B,1,D]
    const float* w_c  = (const float*)d_in[2];  // [D,1]
    const float* w_s  = (const float*)d_in[3];  // [D,D]
    const float* w_r  = (const float*)d_in[4];  // [D,D]
    const float* pos  = (const float*)d_in[5];  // [3000,D]
    const float* w_ap = (const float*)d_in[6];  // [D,1]
    const float* bsc  = (const float*)d_in[7];  // [1]
    float* out = (float*)d_out;

    int B = in_sizes[1] / DD;
    int T = in_sizes[0] / (B * DD);

    fused_kernel<<<B, 512>>>(h, dv, w_c, w_s, w_r, pos, w_ap, bsc, out, B, T);
}